// round 7
// baseline (speedup 1.0000x reference)
#include <cuda_runtime.h>
#include <cuda_fp16.h>
#include <cuda_bf16.h>

// B=4096 scenes, L=200 padded, V=50000, H=128.
// out[i,h] = b[h] + sum_{j<len_i} W[h, tokens[i,j]]
// Wt[V,H] fp16 (L2-resident) + per-scene gather.
// R6: half-warp LDG.128 (2 tokens/warp/load, lane owns 8 h via uint4) +
// fp16 batch accumulator (chain-4) -> ~5 instr/token (was ~10).

#define B_N 4096
#define L_N 200
#define V_N 50000
#define H_N 128

__device__ __half g_Wt[(size_t)V_N * H_N];   // 12.8 MB scratch, [V,H] row-major

// ---------------------------------------------------------------------------
// Tiled transpose+convert: W[H,V] fp32 -> g_Wt[V,H] fp16. half2 stores.
// ---------------------------------------------------------------------------
__global__ void __launch_bounds__(256) transpose_W_kernel(const float* __restrict__ W) {
    __shared__ float tile[32][33];
    int v0 = blockIdx.x * 32;
    int h0 = blockIdx.y * 32;
    int x = threadIdx.x;          // 0..31
    int y = threadIdx.y;          // 0..7

    #pragma unroll
    for (int i = 0; i < 32; i += 8) {
        int v = v0 + x;
        int h = h0 + y + i;
        if (v < V_N) tile[y + i][x] = W[(size_t)h * V_N + v];
    }
    __syncthreads();

    int tid = threadIdx.y * 32 + threadIdx.x;   // 0..255
    int hp  = tid & 15;                         // h-pair index 0..15
    #pragma unroll
    for (int iter = 0; iter < 2; iter++) {
        int vloc = iter * 16 + (tid >> 4);      // 0..31
        int v = v0 + vloc;
        if (v < V_N) {
            __half2 val = __floats2half2_rn(tile[2 * hp][vloc], tile[2 * hp + 1][vloc]);
            *reinterpret_cast<__half2*>(&g_Wt[(size_t)v * H_N + h0 + 2 * hp]) = val;
        }
    }
}

// ---------------------------------------------------------------------------
// Gather-sum: one block (4 warps) per scene; warp w owns 32-token chunks at
// 32w, striding 128. Half-warp per token: lanes 0-15 even token of a pair,
// lanes 16-31 odd token; lane covers h = 8*(lane&15)..+7 via one uint4.
// fp16 accumulate within a 4-pair batch, flush to fp32 per batch.
// ---------------------------------------------------------------------------
__global__ void __launch_bounds__(128, 12) bow_gather_kernel(
    const int* __restrict__ tokens,
    const int* __restrict__ lengths,
    const float* __restrict__ bias,
    float* __restrict__ out)
{
    __shared__ float sh[3][16][9];   // warp partials, padded vs bank conflicts

    int scene = blockIdx.x;
    int wid   = threadIdx.x >> 5;    // 0..3
    int lane  = threadIdx.x & 31;
    int half  = lane >> 4;           // which token of the pair this lane serves
    unsigned laneOff = (unsigned)(lane & 15) * 16u;   // byte offset in 256B row

    int len = lengths[scene];
    const int* tok = tokens + (size_t)scene * L_N;
    const char* WtB = reinterpret_cast<const char*>(g_Wt);

    float accf[8];
    #pragma unroll
    for (int i = 0; i < 8; i++) accf[i] = 0.f;

    for (int base = wid * 32; base < len; base += 128) {
        int m = len - base;
        if (m > 32) m = 32;
        int jj = base + lane;
        int myTok = tok[jj < L_N ? jj : (L_N - 1)];   // coalesced chunk

        if (m == 32) {
            // 16 pairs = 4 batches of 4 pairs (8 tokens each)
            #pragma unroll
            for (int qq = 0; qq < 16; qq += 4) {
                uint4 w[4];
                #pragma unroll
                for (int k = 0; k < 4; k++) {
                    int src = 2 * (qq + k) + half;
                    int t = __shfl_sync(0xffffffffu, myTok, src);
                    w[k] = *reinterpret_cast<const uint4*>(WtB + (unsigned)t * 256u + laneOff);
                }
                __half2 a0 = *reinterpret_cast<__half2*>(&w[0].x);
                __half2 a1 = *reinterpret_cast<__half2*>(&w[0].y);
                __half2 a2 = *reinterpret_cast<__half2*>(&w[0].z);
                __half2 a3 = *reinterpret_cast<__half2*>(&w[0].w);
                #pragma unroll
                for (int k = 1; k < 4; k++) {
                    a0 = __hadd2(a0, *reinterpret_cast<__half2*>(&w[k].x));
                    a1 = __hadd2(a1, *reinterpret_cast<__half2*>(&w[k].y));
                    a2 = __hadd2(a2, *reinterpret_cast<__half2*>(&w[k].z));
                    a3 = __hadd2(a3, *reinterpret_cast<__half2*>(&w[k].w));
                }
                float2 f;
                f = __half22float2(a0); accf[0] += f.x; accf[1] += f.y;
                f = __half22float2(a1); accf[2] += f.x; accf[3] += f.y;
                f = __half22float2(a2); accf[4] += f.x; accf[5] += f.y;
                f = __half22float2(a3); accf[6] += f.x; accf[7] += f.y;
            }
        } else {
            int npair = m >> 1;
            for (int q = 0; q < npair; q++) {
                int src = 2 * q + half;
                int t = __shfl_sync(0xffffffffu, myTok, src);
                uint4 w = *reinterpret_cast<const uint4*>(WtB + (unsigned)t * 256u + laneOff);
                float2 f;
                f = __half22float2(*reinterpret_cast<__half2*>(&w.x)); accf[0] += f.x; accf[1] += f.y;
                f = __half22float2(*reinterpret_cast<__half2*>(&w.y)); accf[2] += f.x; accf[3] += f.y;
                f = __half22float2(*reinterpret_cast<__half2*>(&w.z)); accf[4] += f.x; accf[5] += f.y;
                f = __half22float2(*reinterpret_cast<__half2*>(&w.w)); accf[6] += f.x; accf[7] += f.y;
            }
            if (m & 1) {
                int t = __shfl_sync(0xffffffffu, myTok, m - 1);   // before divergence
                if (half == 0) {
                    uint4 w = *reinterpret_cast<const uint4*>(WtB + (unsigned)t * 256u + laneOff);
                    float2 f;
                    f = __half22float2(*reinterpret_cast<__half2*>(&w.x)); accf[0] += f.x; accf[1] += f.y;
                    f = __half22float2(*reinterpret_cast<__half2*>(&w.y)); accf[2] += f.x; accf[3] += f.y;
                    f = __half22float2(*reinterpret_cast<__half2*>(&w.z)); accf[4] += f.x; accf[5] += f.y;
                    f = __half22float2(*reinterpret_cast<__half2*>(&w.w)); accf[6] += f.x; accf[7] += f.y;
                }
            }
        }
    }

    // Merge the two half-warps (both own the same h range).
    #pragma unroll
    for (int i = 0; i < 8; i++)
        accf[i] += __shfl_down_sync(0xffffffffu, accf[i], 16);

    // Block reduce: warps 1-3 -> smem, warp 0 combines + bias + store.
    if (wid != 0 && lane < 16) {
        #pragma unroll
        for (int i = 0; i < 8; i++) sh[wid - 1][lane][i] = accf[i];
    }
    __syncthreads();
    if (wid == 0 && lane < 16) {
        #pragma unroll
        for (int w = 0; w < 3; w++)
            #pragma unroll
            for (int i = 0; i < 8; i++) accf[i] += sh[w][lane][i];

        const float4* b4 = reinterpret_cast<const float4*>(bias);
        float4 blo = b4[2 * lane], bhi = b4[2 * lane + 1];
        float4 olo = make_float4(accf[0] + blo.x, accf[1] + blo.y,
                                 accf[2] + blo.z, accf[3] + blo.w);
        float4 ohi = make_float4(accf[4] + bhi.x, accf[5] + bhi.y,
                                 accf[6] + bhi.z, accf[7] + bhi.w);
        float4* orow = reinterpret_cast<float4*>(out + (size_t)scene * H_N);
        orow[2 * lane]     = olo;
        orow[2 * lane + 1] = ohi;
    }
}

// ---------------------------------------------------------------------------
extern "C" void kernel_launch(void* const* d_in, const int* in_sizes, int n_in,
                              void* d_out, int out_size) {
    const int*   tokens  = (const int*)d_in[0];
    const int*   lengths = (const int*)d_in[1];
    const float* W       = (const float*)d_in[2];
    const float* bias    = (const float*)d_in[3];
    float*       out     = (float*)d_out;

    (void)in_sizes; (void)n_in; (void)out_size;

    dim3 tgrid((V_N + 31) / 32, H_N / 32);
    dim3 tblock(32, 8);
    transpose_W_kernel<<<tgrid, tblock>>>(W);

    bow_gather_kernel<<<B_N, 128>>>(tokens, lengths, bias, out);
}

// round 9
// speedup vs baseline: 1.0028x; 1.0028x over previous
#include <cuda_runtime.h>
#include <cuda_fp16.h>
#include <cuda_bf16.h>

// B=4096 scenes, L=200 padded, V=50000, H=128.
// out[i,h] = b[h] + sum_{j<len_i} W[h, tokens[i,j]]
// Wt[V,H] fp16 (L2-resident) + per-scene gather.
// R7/R8: combine R6's instruction mix (half-warp LDG.128, ~5 instr/token)
// with R5's latency hiding (8 loads = 4KB in flight per warp). Chain-4 fp16
// group accumulate (R6-measured rel_err 3.6e-4), fp32 across groups.
// (R8 = identical resubmit of R7; R8 bench was an infra failure.)

#define B_N 4096
#define L_N 200
#define V_N 50000
#define H_N 128

__device__ __half g_Wt[(size_t)V_N * H_N];   // 12.8 MB scratch, [V,H] row-major

// ---------------------------------------------------------------------------
// Tiled transpose+convert: W[H,V] fp32 -> g_Wt[V,H] fp16. half2 stores.
// ---------------------------------------------------------------------------
__global__ void __launch_bounds__(256) transpose_W_kernel(const float* __restrict__ W) {
    __shared__ float tile[32][33];
    int v0 = blockIdx.x * 32;
    int h0 = blockIdx.y * 32;
    int x = threadIdx.x;          // 0..31
    int y = threadIdx.y;          // 0..7

    #pragma unroll
    for (int i = 0; i < 32; i += 8) {
        int v = v0 + x;
        int h = h0 + y + i;
        if (v < V_N) tile[y + i][x] = W[(size_t)h * V_N + v];
    }
    __syncthreads();

    int tid = threadIdx.y * 32 + threadIdx.x;   // 0..255
    int hp  = tid & 15;                         // h-pair index 0..15
    #pragma unroll
    for (int iter = 0; iter < 2; iter++) {
        int vloc = iter * 16 + (tid >> 4);      // 0..31
        int v = v0 + vloc;
        if (v < V_N) {
            __half2 val = __floats2half2_rn(tile[2 * hp][vloc], tile[2 * hp + 1][vloc]);
            *reinterpret_cast<__half2*>(&g_Wt[(size_t)v * H_N + h0 + 2 * hp]) = val;
        }
    }
}

// ---------------------------------------------------------------------------
// Gather-sum: one block (4 warps) per scene; warp w owns 32-token chunks at
// 32w, striding 128. Half-warp per token: lanes 0-15 serve the even token of
// a pair, lanes 16-31 the odd one; lane covers h = 8*(lane&15)..+7 (uint4).
// Batches of 8 LDG.128 (16 tokens, 4KB in flight). Two chain-4 fp16 groups
// per batch, each flushed to fp32.
// ---------------------------------------------------------------------------
__global__ void __launch_bounds__(128, 9) bow_gather_kernel(
    const int* __restrict__ tokens,
    const int* __restrict__ lengths,
    const float* __restrict__ bias,
    float* __restrict__ out)
{
    __shared__ float sh[3][16][9];   // warp partials, padded vs bank conflicts

    int scene = blockIdx.x;
    int wid   = threadIdx.x >> 5;    // 0..3
    int lane  = threadIdx.x & 31;
    int half  = lane >> 4;           // which token of a pair this lane serves
    unsigned laneOff = (unsigned)(lane & 15) * 16u;   // byte offset in 256B row

    int len = lengths[scene];
    const int* tok = tokens + (size_t)scene * L_N;
    const char* WtB = reinterpret_cast<const char*>(g_Wt);

    float accf[8];
    #pragma unroll
    for (int i = 0; i < 8; i++) accf[i] = 0.f;

    for (int base = wid * 32; base < len; base += 128) {
        int m = len - base;
        if (m > 32) m = 32;
        int jj = base + lane;
        int myTok = tok[jj < L_N ? jj : (L_N - 1)];   // coalesced chunk

        if (m == 32) {
            // 32 tokens = 2 batches of 8 LDG.128 (16 tokens each)
            #pragma unroll
            for (int qq = 0; qq < 32; qq += 16) {
                uint4 w[8];
                #pragma unroll
                for (int k = 0; k < 8; k++) {
                    int src = qq + 2 * k + half;
                    int t = __shfl_sync(0xffffffffu, myTok, src);
                    w[k] = *reinterpret_cast<const uint4*>(WtB + (unsigned)t * 256u + laneOff);
                }
                // Two chain-4 fp16 groups, each flushed to fp32.
                #pragma unroll
                for (int g = 0; g < 2; g++) {
                    uint4* wg = &w[4 * g];
                    __half2 a0 = *reinterpret_cast<__half2*>(&wg[0].x);
                    __half2 a1 = *reinterpret_cast<__half2*>(&wg[0].y);
                    __half2 a2 = *reinterpret_cast<__half2*>(&wg[0].z);
                    __half2 a3 = *reinterpret_cast<__half2*>(&wg[0].w);
                    #pragma unroll
                    for (int k = 1; k < 4; k++) {
                        a0 = __hadd2(a0, *reinterpret_cast<__half2*>(&wg[k].x));
                        a1 = __hadd2(a1, *reinterpret_cast<__half2*>(&wg[k].y));
                        a2 = __hadd2(a2, *reinterpret_cast<__half2*>(&wg[k].z));
                        a3 = __hadd2(a3, *reinterpret_cast<__half2*>(&wg[k].w));
                    }
                    float2 f;
                    f = __half22float2(a0); accf[0] += f.x; accf[1] += f.y;
                    f = __half22float2(a1); accf[2] += f.x; accf[3] += f.y;
                    f = __half22float2(a2); accf[4] += f.x; accf[5] += f.y;
                    f = __half22float2(a3); accf[6] += f.x; accf[7] += f.y;
                }
            }
        } else {
            int npair = m >> 1;
            for (int q = 0; q < npair; q++) {
                int src = 2 * q + half;
                int t = __shfl_sync(0xffffffffu, myTok, src);
                uint4 w = *reinterpret_cast<const uint4*>(WtB + (unsigned)t * 256u + laneOff);
                float2 f;
                f = __half22float2(*reinterpret_cast<__half2*>(&w.x)); accf[0] += f.x; accf[1] += f.y;
                f = __half22float2(*reinterpret_cast<__half2*>(&w.y)); accf[2] += f.x; accf[3] += f.y;
                f = __half22float2(*reinterpret_cast<__half2*>(&w.z)); accf[4] += f.x; accf[5] += f.y;
                f = __half22float2(*reinterpret_cast<__half2*>(&w.w)); accf[6] += f.x; accf[7] += f.y;
            }
            if (m & 1) {
                int t = __shfl_sync(0xffffffffu, myTok, m - 1);   // before divergence
                if (half == 0) {
                    uint4 w = *reinterpret_cast<const uint4*>(WtB + (unsigned)t * 256u + laneOff);
                    float2 f;
                    f = __half22float2(*reinterpret_cast<__half2*>(&w.x)); accf[0] += f.x; accf[1] += f.y;
                    f = __half22float2(*reinterpret_cast<__half2*>(&w.y)); accf[2] += f.x; accf[3] += f.y;
                    f = __half22float2(*reinterpret_cast<__half2*>(&w.z)); accf[4] += f.x; accf[5] += f.y;
                    f = __half22float2(*reinterpret_cast<__half2*>(&w.w)); accf[6] += f.x; accf[7] += f.y;
                }
            }
        }
    }

    // Merge the two half-warps (both own the same h range).
    #pragma unroll
    for (int i = 0; i < 8; i++)
        accf[i] += __shfl_down_sync(0xffffffffu, accf[i], 16);

    // Block reduce: warps 1-3 -> smem, warp 0 combines + bias + store.
    if (wid != 0 && lane < 16) {
        #pragma unroll
        for (int i = 0; i < 8; i++) sh[wid - 1][lane][i] = accf[i];
    }
    __syncthreads();
    if (wid == 0 && lane < 16) {
        #pragma unroll
        for (int w = 0; w < 3; w++)
            #pragma unroll
            for (int i = 0; i < 8; i++) accf[i] += sh[w][lane][i];

        const float4* b4 = reinterpret_cast<const float4*>(bias);
        float4 blo = b4[2 * lane], bhi = b4[2 * lane + 1];
        float4 olo = make_float4(accf[0] + blo.x, accf[1] + blo.y,
                                 accf[2] + blo.z, accf[3] + blo.w);
        float4 ohi = make_float4(accf[4] + bhi.x, accf[5] + bhi.y,
                                 accf[6] + bhi.z, accf[7] + bhi.w);
        float4* orow = reinterpret_cast<float4*>(out + (size_t)scene * H_N);
        orow[2 * lane]     = olo;
        orow[2 * lane + 1] = ohi;
    }
}

// ---------------------------------------------------------------------------
extern "C" void kernel_launch(void* const* d_in, const int* in_sizes, int n_in,
                              void* d_out, int out_size) {
    const int*   tokens  = (const int*)d_in[0];
    const int*   lengths = (const int*)d_in[1];
    const float* W       = (const float*)d_in[2];
    const float* bias    = (const float*)d_in[3];
    float*       out     = (float*)d_out;

    (void)in_sizes; (void)n_in; (void)out_size;

    dim3 tgrid((V_N + 31) / 32, H_N / 32);
    dim3 tblock(32, 8);
    transpose_W_kernel<<<tgrid, tblock>>>(W);

    bow_gather_kernel<<<B_N, 128>>>(tokens, lengths, bias, out);
}

// round 10
// speedup vs baseline: 1.0057x; 1.0028x over previous
#include <cuda_runtime.h>
#include <cuda_fp16.h>
#include <cuda_bf16.h>

// B=4096 scenes, L=200 padded, V=50000, H=128.
// out[i,h] = b[h] + sum_{j<len_i} W[h, tokens[i,j]]
// Wt[V,H] fp16 (L2-resident) + per-scene gather.
// R9: R5's proven load shape (uniform 32-lane LDG.64, one token per load,
// 8-deep batches = MLP 8) + chain-4 fp16 pre-reduction from R6 to cut the
// issue work ~30%. Divergent half-warp LDG.128 (R6/R7) measured SLOWER -> dropped.

#define B_N 4096
#define L_N 200
#define V_N 50000
#define H_N 128

__device__ __half g_Wt[(size_t)V_N * H_N];   // 12.8 MB scratch, [V,H] row-major

// ---------------------------------------------------------------------------
// Tiled transpose+convert: W[H,V] fp32 -> g_Wt[V,H] fp16. half2 stores.
// ---------------------------------------------------------------------------
__global__ void __launch_bounds__(256) transpose_W_kernel(const float* __restrict__ W) {
    __shared__ float tile[32][33];
    int v0 = blockIdx.x * 32;
    int h0 = blockIdx.y * 32;
    int x = threadIdx.x;          // 0..31
    int y = threadIdx.y;          // 0..7

    #pragma unroll
    for (int i = 0; i < 32; i += 8) {
        int v = v0 + x;
        int h = h0 + y + i;
        if (v < V_N) tile[y + i][x] = W[(size_t)h * V_N + v];
    }
    __syncthreads();

    int tid = threadIdx.y * 32 + threadIdx.x;   // 0..255
    int hp  = tid & 15;                         // h-pair index 0..15
    #pragma unroll
    for (int iter = 0; iter < 2; iter++) {
        int vloc = iter * 16 + (tid >> 4);      // 0..31
        int v = v0 + vloc;
        if (v < V_N) {
            __half2 val = __floats2half2_rn(tile[2 * hp][vloc], tile[2 * hp + 1][vloc]);
            *reinterpret_cast<__half2*>(&g_Wt[(size_t)v * H_N + h0 + 2 * hp]) = val;
        }
    }
}

// ---------------------------------------------------------------------------
// Gather-sum: one block (4 warps) per scene; warp w owns 32-token chunks at
// 32w, striding 128. Lane owns h = 4*lane..4*lane+3 (uint2 = 4 halves).
// One token per warp-LDG.64 (uniform addresses, 2 lines). Batches of 8 loads
// (MLP 8); two chain-4 HADD2 groups per batch, each flushed to fp32.
// ---------------------------------------------------------------------------
__global__ void __launch_bounds__(128, 10) bow_gather_kernel(
    const int* __restrict__ tokens,
    const int* __restrict__ lengths,
    const float* __restrict__ bias,
    float* __restrict__ out)
{
    __shared__ float4 sh[3][32];

    int scene = blockIdx.x;
    int wid   = threadIdx.x >> 5;
    int lane  = threadIdx.x & 31;

    int len = lengths[scene];
    const int* tok = tokens + (size_t)scene * L_N;
    const char* WtB = reinterpret_cast<const char*>(g_Wt);
    unsigned laneOff = (unsigned)lane * 8u;   // byte offset of lane's 4 halves

    float4 acc = make_float4(0.f, 0.f, 0.f, 0.f);

    for (int base = wid * 32; base < len; base += 128) {
        int m = len - base;
        if (m > 32) m = 32;
        int jj = base + lane;
        int myTok = tok[jj < L_N ? jj : (L_N - 1)];   // coalesced chunk

        if (m == 32) {
            // 32 tokens = 4 batches of 8 LDG.64 (MLP 8)
            #pragma unroll
            for (int kk = 0; kk < 32; kk += 8) {
                uint2 w[8];
                #pragma unroll
                for (int k = 0; k < 8; k++) {
                    int t = __shfl_sync(0xffffffffu, myTok, kk + k);
                    w[k] = *reinterpret_cast<const uint2*>(WtB + (unsigned)t * 256u + laneOff);
                }
                // Two chain-4 fp16 groups, each flushed to fp32.
                #pragma unroll
                for (int g = 0; g < 2; g++) {
                    uint2* wg = &w[4 * g];
                    __half2 a0 = *reinterpret_cast<__half2*>(&wg[0].x);
                    __half2 a1 = *reinterpret_cast<__half2*>(&wg[0].y);
                    #pragma unroll
                    for (int k = 1; k < 4; k++) {
                        a0 = __hadd2(a0, *reinterpret_cast<__half2*>(&wg[k].x));
                        a1 = __hadd2(a1, *reinterpret_cast<__half2*>(&wg[k].y));
                    }
                    float2 f01 = __half22float2(a0);
                    float2 f23 = __half22float2(a1);
                    acc.x += f01.x; acc.y += f01.y;
                    acc.z += f23.x; acc.w += f23.y;
                }
            }
        } else {
            for (int k = 0; k < m; k++) {
                int t = __shfl_sync(0xffffffffu, myTok, k);
                uint2 w = *reinterpret_cast<const uint2*>(WtB + (unsigned)t * 256u + laneOff);
                float2 f01 = __half22float2(*reinterpret_cast<__half2*>(&w.x));
                float2 f23 = __half22float2(*reinterpret_cast<__half2*>(&w.y));
                acc.x += f01.x; acc.y += f01.y;
                acc.z += f23.x; acc.w += f23.y;
            }
        }
    }

    // Block reduce: warps 1-3 -> smem, warp 0 combines + bias + store.
    if (wid != 0) sh[wid - 1][lane] = acc;
    __syncthreads();
    if (wid == 0) {
        float4 b4 = reinterpret_cast<const float4*>(bias)[lane];
        #pragma unroll
        for (int w = 0; w < 3; w++) {
            float4 p = sh[w][lane];
            acc.x += p.x; acc.y += p.y; acc.z += p.z; acc.w += p.w;
        }
        acc.x += b4.x; acc.y += b4.y; acc.z += b4.z; acc.w += b4.w;
        reinterpret_cast<float4*>(out + (size_t)scene * H_N)[lane] = acc;
    }
}

// ---------------------------------------------------------------------------
extern "C" void kernel_launch(void* const* d_in, const int* in_sizes, int n_in,
                              void* d_out, int out_size) {
    const int*   tokens  = (const int*)d_in[0];
    const int*   lengths = (const int*)d_in[1];
    const float* W       = (const float*)d_in[2];
    const float* bias    = (const float*)d_in[3];
    float*       out     = (float*)d_out;

    (void)in_sizes; (void)n_in; (void)out_size;

    dim3 tgrid((V_N + 31) / 32, H_N / 32);
    dim3 tblock(32, 8);
    transpose_W_kernel<<<tgrid, tblock>>>(W);

    bow_gather_kernel<<<B_N, 128>>>(tokens, lengths, bias, out);
}